// round 6
// baseline (speedup 1.0000x reference)
#include <cuda_runtime.h>
#include <cuda_bf16.h>

// Problem constants (GCN2: N=50000 nodes, E=800000 edges, 128 -> 128 -> 64)
#define NMAX 50000
#define EMAX 800000
#define DIN  128
#define DHID 128
#define DOUT 64

// ---------------- scratch (device globals; no allocations allowed) ----------
__device__ int   g_is64;             // 1 if edge_index is int64, 0 if int32
__device__ int   g_deg[NMAX];
__device__ int   g_rowptr[NMAX + 1];
__device__ int   g_cursor[NMAX];
__device__ __align__(16) int2  g_csr[EMAX];   // {src, dinv[src] as bits}
__device__ float g_dinv[NMAX];
__device__ __align__(16) float g_h1[NMAX * DHID];  // x @ W1
__device__ __align__(16) float g_a1[NMAX * DHID];  // relu(conv1)
__device__ __align__(16) float g_h2[NMAX * DOUT];  // a1 @ W2

// ---------------- edge index decoding ---------------------------------------
// The reference creates edge_index with dtype=int64 under default JAX config
// (x64 disabled), which usually downgrades to int32 — but detect at runtime:
// an int64 non-negative array viewed as int32 words has all odd words == 0.
__global__ void detect_kernel(const int* __restrict__ ei32) {
    if (threadIdx.x == 0 && blockIdx.x == 0) {
        int is64 = 1;
        for (int i = 0; i < 16; i++)
            if (ei32[2 * i + 1] != 0) { is64 = 0; break; }
        g_is64 = is64;
    }
}

__device__ __forceinline__ int load_edge(const void* ei, long long idx) {
    if (g_is64) return (int)((const long long*)ei)[idx];
    return ((const int*)ei)[idx];
}

__global__ void zero_deg_kernel(int n) {
    int i = blockIdx.x * blockDim.x + threadIdx.x;
    if (i < n) g_deg[i] = 0;
}

__global__ void count_deg_kernel(const void* __restrict__ ei, int E, int n) {
    int e = blockIdx.x * blockDim.x + threadIdx.x;
    if (e < E) {
        int dst = load_edge(ei, (long long)E + e);
        if ((unsigned)dst < (unsigned)n) atomicAdd(&g_deg[dst], 1);
    }
}

__global__ void dinv_kernel(int n) {
    int i = blockIdx.x * blockDim.x + threadIdx.x;
    if (i < n) g_dinv[i] = rsqrtf((float)g_deg[i] + 1.0f);
}

// Single-block exclusive scan of g_deg -> g_rowptr / g_cursor (n up to 50000).
__global__ __launch_bounds__(1024) void scan_kernel(int n) {
    __shared__ int sums[1024];
    int t = threadIdx.x;
    int chunk = (n + 1023) >> 10;
    int beg = t * chunk;
    int end = beg + chunk; if (end > n) end = n;
    if (beg > n) beg = n;

    int s = 0;
    for (int i = beg; i < end; i++) s += g_deg[i];
    sums[t] = s;
    __syncthreads();
    for (int off = 1; off < 1024; off <<= 1) {
        int v = (t >= off) ? sums[t - off] : 0;
        __syncthreads();
        sums[t] += v;
        __syncthreads();
    }
    int run = (t == 0) ? 0 : sums[t - 1];
    for (int i = beg; i < end; i++) {
        g_rowptr[i] = run;
        g_cursor[i] = run;
        run += g_deg[i];
    }
    if (t == 1023) g_rowptr[n] = sums[1023];
}

__global__ void fill_csr_kernel(const void* __restrict__ ei, int E, int n) {
    int e = blockIdx.x * blockDim.x + threadIdx.x;
    if (e < E) {
        int src = load_edge(ei, e);
        int dst = load_edge(ei, (long long)E + e);
        if ((unsigned)src < (unsigned)n && (unsigned)dst < (unsigned)n) {
            int pos = atomicAdd(&g_cursor[dst], 1);
            g_csr[pos] = make_int2(src, __float_as_int(g_dinv[src]));
        }
    }
}

// ---------------- dense GEMM: H[n, NCOLS] = X[n, 128] @ W[128, NCOLS] -------
// 128x64 block tile, 8x4 register micro-tile, KC=16, 8 K-slabs, 256 threads.
// As stored k-major ([k][row], row stride 132: 16B-aligned rows).
// Register-prefetch double buffering hides the per-slab global-load latency.
template <int NCOLS>
__global__ __launch_bounds__(256) void gemm_kernel(const float* __restrict__ X,
                                                   const float* __restrict__ W,
                                                   float* __restrict__ H, int n) {
    __shared__ __align__(16) float As[16][132];  // [k][row 0..127]
    __shared__ __align__(16) float Bs[16][64];   // [k][col]
    const int tid = threadIdx.x;
    const int tx = tid & 15;       // col group 0..15 -> cols tx*4..tx*4+3
    const int ty = tid >> 4;       // row group 0..15 -> rows ty*8..ty*8+7
    const int r0 = blockIdx.x * 128;
    const int c0 = blockIdx.y * 64;

    int a_r[8], a_k[8], b_k[4], b_c[4];
#pragma unroll
    for (int j = 0; j < 8; j++) {
        int i = tid + j * 256;
        a_r[j] = i >> 4; a_k[j] = i & 15;
    }
#pragma unroll
    for (int j = 0; j < 4; j++) {
        int i = tid + j * 256;
        b_k[j] = i >> 6; b_c[j] = i & 63;
    }

    float acc[8][4];
#pragma unroll
    for (int j = 0; j < 8; j++)
#pragma unroll
        for (int i = 0; i < 4; i++) acc[j][i] = 0.0f;

    float ra[8], rb[4];
#pragma unroll
    for (int j = 0; j < 8; j++) {
        int gr = r0 + a_r[j];
        ra[j] = (gr < n) ? X[gr * 128 + a_k[j]] : 0.0f;
    }
#pragma unroll
    for (int j = 0; j < 4; j++)
        rb[j] = W[b_k[j] * NCOLS + c0 + b_c[j]];
#pragma unroll
    for (int j = 0; j < 8; j++) As[a_k[j]][a_r[j]] = ra[j];
#pragma unroll
    for (int j = 0; j < 4; j++) Bs[b_k[j]][b_c[j]] = rb[j];
    __syncthreads();

    for (int k0 = 16; k0 <= 128; k0 += 16) {
        bool more = (k0 < 128);
        if (more) {
#pragma unroll
            for (int j = 0; j < 8; j++) {
                int gr = r0 + a_r[j];
                ra[j] = (gr < n) ? X[gr * 128 + k0 + a_k[j]] : 0.0f;
            }
#pragma unroll
            for (int j = 0; j < 4; j++)
                rb[j] = W[(k0 + b_k[j]) * NCOLS + c0 + b_c[j]];
        }
#pragma unroll
        for (int kk = 0; kk < 16; kk++) {
            float4 a0 = *(const float4*)&As[kk][ty * 8];
            float4 a1 = *(const float4*)&As[kk][ty * 8 + 4];
            float4 b  = *(const float4*)&Bs[kk][tx * 4];
            acc[0][0] += a0.x * b.x; acc[0][1] += a0.x * b.y; acc[0][2] += a0.x * b.z; acc[0][3] += a0.x * b.w;
            acc[1][0] += a0.y * b.x; acc[1][1] += a0.y * b.y; acc[1][2] += a0.y * b.z; acc[1][3] += a0.y * b.w;
            acc[2][0] += a0.z * b.x; acc[2][1] += a0.z * b.y; acc[2][2] += a0.z * b.z; acc[2][3] += a0.z * b.w;
            acc[3][0] += a0.w * b.x; acc[3][1] += a0.w * b.y; acc[3][2] += a0.w * b.z; acc[3][3] += a0.w * b.w;
            acc[4][0] += a1.x * b.x; acc[4][1] += a1.x * b.y; acc[4][2] += a1.x * b.z; acc[4][3] += a1.x * b.w;
            acc[5][0] += a1.y * b.x; acc[5][1] += a1.y * b.y; acc[5][2] += a1.y * b.z; acc[5][3] += a1.y * b.w;
            acc[6][0] += a1.z * b.x; acc[6][1] += a1.z * b.y; acc[6][2] += a1.z * b.z; acc[6][3] += a1.z * b.w;
            acc[7][0] += a1.w * b.x; acc[7][1] += a1.w * b.y; acc[7][2] += a1.w * b.z; acc[7][3] += a1.w * b.w;
        }
        __syncthreads();
        if (more) {
#pragma unroll
            for (int j = 0; j < 8; j++) As[a_k[j]][a_r[j]] = ra[j];
#pragma unroll
            for (int j = 0; j < 4; j++) Bs[b_k[j]][b_c[j]] = rb[j];
            __syncthreads();
        }
    }

#pragma unroll
    for (int j = 0; j < 8; j++) {
        int gr = r0 + ty * 8 + j;
        if (gr < n) {
            float4 o = make_float4(acc[j][0], acc[j][1], acc[j][2], acc[j][3]);
            *(float4*)&H[gr * NCOLS + c0 + tx * 4] = o;
        }
    }
}

// ---------------- CSR aggregation (warp per node) ----------------------------
// out[d] = dinv[d] * sum_e dinv[s]*H[s] + dinv[d]^2 * H[d] + bias  (opt relu)
// Edge loop unrolled x4 with independent accumulators -> MLP_eff ~= 4 on the
// L2-resident row gathers.
__global__ __launch_bounds__(256) void agg128_kernel(const float* __restrict__ H,
                                                     const float* __restrict__ bias,
                                                     float* __restrict__ out,
                                                     int n, int do_relu) {
    int warp = (blockIdx.x * blockDim.x + threadIdx.x) >> 5;
    int lane = threadIdx.x & 31;
    if (warp >= n) return;

    float4 acc0 = make_float4(0.f, 0.f, 0.f, 0.f);
    float4 acc1 = make_float4(0.f, 0.f, 0.f, 0.f);
    float4 acc2 = make_float4(0.f, 0.f, 0.f, 0.f);
    float4 acc3 = make_float4(0.f, 0.f, 0.f, 0.f);
    int beg = g_rowptr[warp], end = g_rowptr[warp + 1];
    const float4* H4 = (const float4*)H;
    int p = beg;
    for (; p + 3 < end; p += 4) {
        int2 e0 = g_csr[p];
        int2 e1 = g_csr[p + 1];
        int2 e2 = g_csr[p + 2];
        int2 e3 = g_csr[p + 3];
        float4 v0 = H4[e0.x * 32 + lane];
        float4 v1 = H4[e1.x * 32 + lane];
        float4 v2 = H4[e2.x * 32 + lane];
        float4 v3 = H4[e3.x * 32 + lane];
        float w0 = __int_as_float(e0.y);
        float w1 = __int_as_float(e1.y);
        float w2 = __int_as_float(e2.y);
        float w3 = __int_as_float(e3.y);
        acc0.x += w0 * v0.x; acc0.y += w0 * v0.y; acc0.z += w0 * v0.z; acc0.w += w0 * v0.w;
        acc1.x += w1 * v1.x; acc1.y += w1 * v1.y; acc1.z += w1 * v1.z; acc1.w += w1 * v1.w;
        acc2.x += w2 * v2.x; acc2.y += w2 * v2.y; acc2.z += w2 * v2.z; acc2.w += w2 * v2.w;
        acc3.x += w3 * v3.x; acc3.y += w3 * v3.y; acc3.z += w3 * v3.z; acc3.w += w3 * v3.w;
    }
    for (; p < end; p++) {
        int2 e0 = g_csr[p];
        float4 v0 = H4[e0.x * 32 + lane];
        float w0 = __int_as_float(e0.y);
        acc0.x += w0 * v0.x; acc0.y += w0 * v0.y; acc0.z += w0 * v0.z; acc0.w += w0 * v0.w;
    }
    acc0.x += acc1.x + acc2.x + acc3.x;
    acc0.y += acc1.y + acc2.y + acc3.y;
    acc0.z += acc1.z + acc2.z + acc3.z;
    acc0.w += acc1.w + acc2.w + acc3.w;

    float di = g_dinv[warp];
    float d2 = di * di;
    float4 hv = H4[warp * 32 + lane];
    float4 bv = ((const float4*)bias)[lane];
    float4 o;
    o.x = di * acc0.x + d2 * hv.x + bv.x;
    o.y = di * acc0.y + d2 * hv.y + bv.y;
    o.z = di * acc0.z + d2 * hv.z + bv.z;
    o.w = di * acc0.w + d2 * hv.w + bv.w;
    if (do_relu) {
        o.x = fmaxf(o.x, 0.f); o.y = fmaxf(o.y, 0.f);
        o.z = fmaxf(o.z, 0.f); o.w = fmaxf(o.w, 0.f);
    }
    ((float4*)out)[warp * 32 + lane] = o;
}

__global__ __launch_bounds__(256) void agg64_kernel(const float* __restrict__ H,
                                                    const float* __restrict__ bias,
                                                    float* __restrict__ out, int n) {
    int warp = (blockIdx.x * blockDim.x + threadIdx.x) >> 5;
    int lane = threadIdx.x & 31;
    if (warp >= n) return;

    float2 acc0 = make_float2(0.f, 0.f);
    float2 acc1 = make_float2(0.f, 0.f);
    float2 acc2 = make_float2(0.f, 0.f);
    float2 acc3 = make_float2(0.f, 0.f);
    int beg = g_rowptr[warp], end = g_rowptr[warp + 1];
    const float2* H2 = (const float2*)H;
    int p = beg;
    for (; p + 3 < end; p += 4) {
        int2 e0 = g_csr[p];
        int2 e1 = g_csr[p + 1];
        int2 e2 = g_csr[p + 2];
        int2 e3 = g_csr[p + 3];
        float2 v0 = H2[e0.x * 32 + lane];
        float2 v1 = H2[e1.x * 32 + lane];
        float2 v2 = H2[e2.x * 32 + lane];
        float2 v3 = H2[e3.x * 32 + lane];
        float w0 = __int_as_float(e0.y);
        float w1 = __int_as_float(e1.y);
        float w2 = __int_as_float(e2.y);
        float w3 = __int_as_float(e3.y);
        acc0.x += w0 * v0.x; acc0.y += w0 * v0.y;
        acc1.x += w1 * v1.x; acc1.y += w1 * v1.y;
        acc2.x += w2 * v2.x; acc2.y += w2 * v2.y;
        acc3.x += w3 * v3.x; acc3.y += w3 * v3.y;
    }
    for (; p < end; p++) {
        int2 e0 = g_csr[p];
        float2 v0 = H2[e0.x * 32 + lane];
        float w0 = __int_as_float(e0.y);
        acc0.x += w0 * v0.x; acc0.y += w0 * v0.y;
    }
    acc0.x += acc1.x + acc2.x + acc3.x;
    acc0.y += acc1.y + acc2.y + acc3.y;

    float di = g_dinv[warp];
    float d2 = di * di;
    float2 hv = H2[warp * 32 + lane];
    float2 bv = ((const float2*)bias)[lane];
    float2 o;
    o.x = di * acc0.x + d2 * hv.x + bv.x;
    o.y = di * acc0.y + d2 * hv.y + bv.y;
    ((float2*)out)[warp * 32 + lane] = o;
}

// ---------------- launch ------------------------------------------------------
extern "C" void kernel_launch(void* const* d_in, const int* in_sizes, int n_in,
                              void* d_out, int out_size) {
    const float* x   = (const float*)d_in[0];
    const void*  ei  = d_in[1];
    const float* W1  = (const float*)d_in[2];
    const float* b1  = (const float*)d_in[3];
    const float* W2  = (const float*)d_in[4];
    const float* b2  = (const float*)d_in[5];
    float*       out = (float*)d_out;

    const int N = in_sizes[0] / DIN;   // 50000
    const int E = in_sizes[1] / 2;     // 800000

    void *p_h1, *p_a1, *p_h2;
    cudaGetSymbolAddress(&p_h1, g_h1);
    cudaGetSymbolAddress(&p_a1, g_a1);
    cudaGetSymbolAddress(&p_h2, g_h2);
    float* h1 = (float*)p_h1;
    float* a1 = (float*)p_a1;
    float* h2 = (float*)p_h2;

    // graph build
    detect_kernel<<<1, 32>>>((const int*)ei);
    zero_deg_kernel<<<(N + 255) / 256, 256>>>(N);
    count_deg_kernel<<<(E + 255) / 256, 256>>>(ei, E, N);
    dinv_kernel<<<(N + 255) / 256, 256>>>(N);
    scan_kernel<<<1, 1024>>>(N);
    fill_csr_kernel<<<(E + 255) / 256, 256>>>(ei, E, N);

    // layer 1: h1 = x @ W1 ; a1 = relu(conv1(h1))
    {
        dim3 grid((N + 127) / 128, DHID / 64);
        gemm_kernel<DHID><<<grid, 256>>>(x, W1, h1, N);
    }
    agg128_kernel<<<(N + 7) / 8, 256>>>(h1, b1, a1, N, 1);

    // layer 2: h2 = a1 @ W2 ; out = conv2(h2)
    {
        dim3 grid((N + 127) / 128, DOUT / 64);
        gemm_kernel<DOUT><<<grid, 256>>>(a1, W2, h2, N);
    }
    agg64_kernel<<<(N + 7) / 8, 256>>>(h2, b2, out, N);
}

// round 9
// speedup vs baseline: 1.3965x; 1.3965x over previous
#include <cuda_runtime.h>
#include <cuda_bf16.h>

// Problem constants (GCN2: N=50000 nodes, E=800000 edges, 128 -> 128 -> 64)
#define NMAX 50000
#define EMAX 800000
#define DIN  128
#define DHID 128
#define DOUT 64
#define NBLK ((NMAX + 255) / 256)   // 196 scan blocks

// ---------------- scratch (device globals; no allocations allowed) ----------
__device__ int   g_is64;             // 1 if edge_index is int64, 0 if int32
__device__ int   g_deg[NMAX];
__device__ int   g_locexc[NMAX];     // per-block exclusive prefix of deg
__device__ int   g_part[NBLK];       // per-block totals -> inclusive scan
__device__ int   g_rowptr[NMAX + 1];
__device__ int   g_cursor[NMAX];
__device__ __align__(16) int2  g_csr[EMAX];   // {src, dinv[src] as bits}
__device__ float g_dinv[NMAX];
__device__ __align__(16) float g_h1[NMAX * DHID];
__device__ __align__(16) float g_a1[NMAX * DHID];
__device__ __align__(16) float g_h2[NMAX * DOUT];

// ---------------- edge dtype detection (warp-parallel) -----------------------
// int64 non-negative indices viewed as int32 words: all odd words are zero.
__global__ void detect_kernel(const int* __restrict__ ei32) {
    int lane = threadIdx.x & 31;
    int v = (lane < 16) ? ei32[2 * lane + 1] : 0;
    unsigned nz = __ballot_sync(0xFFFFFFFF, v != 0);
    if (lane == 0) g_is64 = (nz == 0) ? 1 : 0;
}

__device__ __forceinline__ int load_edge(const void* ei, long long idx) {
    if (g_is64) return (int)((const long long*)ei)[idx];
    return ((const int*)ei)[idx];
}

__global__ void count_deg_kernel(const void* __restrict__ ei, int E, int n) {
    int e = blockIdx.x * blockDim.x + threadIdx.x;
    if (e < E) {
        int dst = load_edge(ei, (long long)E + e);
        if ((unsigned)dst < (unsigned)n) atomicAdd(&g_deg[dst], 1);
    }
}

// ---------------- 3-phase parallel scan of g_deg -----------------------------
// phase 1: per-block (256-wide) exclusive prefix + block total; fused dinv.
__global__ __launch_bounds__(256) void scan1_kernel(int n) {
    __shared__ int s[256];
    int t = threadIdx.x;
    int i = blockIdx.x * 256 + t;
    int d = (i < n) ? g_deg[i] : 0;
    s[t] = d;
    __syncthreads();
#pragma unroll
    for (int off = 1; off < 256; off <<= 1) {
        int v = (t >= off) ? s[t - off] : 0;
        __syncthreads();
        s[t] += v;
        __syncthreads();
    }
    if (i < n) {
        g_locexc[i] = s[t] - d;                 // exclusive within block
        g_dinv[i]   = rsqrtf((float)d + 1.0f);  // fused dinv
    }
    if (t == 255) g_part[blockIdx.x] = s[255];
}

// phase 2: single block inclusive scan of NBLK partials (NBLK <= 256).
__global__ __launch_bounds__(256) void scan2_kernel(int nb) {
    __shared__ int s[256];
    int t = threadIdx.x;
    s[t] = (t < nb) ? g_part[t] : 0;
    __syncthreads();
#pragma unroll
    for (int off = 1; off < 256; off <<= 1) {
        int v = (t >= off) ? s[t - off] : 0;
        __syncthreads();
        s[t] += v;
        __syncthreads();
    }
    if (t < nb) g_part[t] = s[t];
}

// phase 3: scatter rowptr/cursor.
__global__ __launch_bounds__(256) void scan3_kernel(int n, int nb) {
    int b = blockIdx.x;
    int i = b * 256 + threadIdx.x;
    int off = (b == 0) ? 0 : g_part[b - 1];
    if (i < n) {
        int r = off + g_locexc[i];
        g_rowptr[i] = r;
        g_cursor[i] = r;
    }
    if (i == 0) g_rowptr[n] = g_part[nb - 1];
}

__global__ void fill_csr_kernel(const void* __restrict__ ei, int E, int n) {
    int e = blockIdx.x * blockDim.x + threadIdx.x;
    if (e < E) {
        int src = load_edge(ei, e);
        int dst = load_edge(ei, (long long)E + e);
        if ((unsigned)src < (unsigned)n && (unsigned)dst < (unsigned)n) {
            int pos = atomicAdd(&g_cursor[dst], 1);
            g_csr[pos] = make_int2(src, __float_as_int(g_dinv[src]));
        }
    }
}

// ---------------- layer-1 GEMM: H[n,128] = X[n,128] @ W[128,128] -------------
// 128x128 block tile, 8x8 micro-tile, KC=16, 256 threads, register prefetch.
__global__ __launch_bounds__(256, 2) void gemm_l1_kernel(const float* __restrict__ X,
                                                         const float* __restrict__ W,
                                                         float* __restrict__ H, int n) {
    __shared__ __align__(16) float As[16][132];  // [k][row]
    __shared__ __align__(16) float Bs[16][128];  // [k][col]
    const int tid = threadIdx.x;
    const int tx = tid & 15;       // col group -> cols tx*8..tx*8+7
    const int ty = tid >> 4;       // row group -> rows ty*8..ty*8+7
    const int r0 = blockIdx.x * 128;

    float acc[8][8];
#pragma unroll
    for (int i = 0; i < 8; i++)
#pragma unroll
        for (int j = 0; j < 8; j++) acc[i][j] = 0.0f;

    float ra[8], rb[8];
    // preload slab 0 (coords inline: A i=tid+j*256 -> r=i>>4,k=i&15;
    //                 B i=tid+j*256 -> k=i>>7,c=i&127)
#pragma unroll
    for (int j = 0; j < 8; j++) {
        int ia = tid + j * 256;
        int gr = r0 + (ia >> 4);
        ra[j] = (gr < n) ? X[gr * 128 + (ia & 15)] : 0.0f;
        rb[j] = W[(ia >> 7) * 128 + (ia & 127)];
    }
#pragma unroll
    for (int j = 0; j < 8; j++) {
        int ia = tid + j * 256;
        As[ia & 15][ia >> 4] = ra[j];
        Bs[ia >> 7][ia & 127] = rb[j];
    }
    __syncthreads();

    for (int k0 = 16; k0 <= 128; k0 += 16) {
        bool more = (k0 < 128);
        if (more) {
#pragma unroll
            for (int j = 0; j < 8; j++) {
                int ia = tid + j * 256;
                int gr = r0 + (ia >> 4);
                ra[j] = (gr < n) ? X[gr * 128 + k0 + (ia & 15)] : 0.0f;
                rb[j] = W[(k0 + (ia >> 7)) * 128 + (ia & 127)];
            }
        }
#pragma unroll
        for (int kk = 0; kk < 16; kk++) {
            float4 a0 = *(const float4*)&As[kk][ty * 8];
            float4 a1 = *(const float4*)&As[kk][ty * 8 + 4];
            float4 b0 = *(const float4*)&Bs[kk][tx * 8];
            float4 b1 = *(const float4*)&Bs[kk][tx * 8 + 4];
            acc[0][0] += a0.x * b0.x; acc[0][1] += a0.x * b0.y; acc[0][2] += a0.x * b0.z; acc[0][3] += a0.x * b0.w;
            acc[0][4] += a0.x * b1.x; acc[0][5] += a0.x * b1.y; acc[0][6] += a0.x * b1.z; acc[0][7] += a0.x * b1.w;
            acc[1][0] += a0.y * b0.x; acc[1][1] += a0.y * b0.y; acc[1][2] += a0.y * b0.z; acc[1][3] += a0.y * b0.w;
            acc[1][4] += a0.y * b1.x; acc[1][5] += a0.y * b1.y; acc[1][6] += a0.y * b1.z; acc[1][7] += a0.y * b1.w;
            acc[2][0] += a0.z * b0.x; acc[2][1] += a0.z * b0.y; acc[2][2] += a0.z * b0.z; acc[2][3] += a0.z * b0.w;
            acc[2][4] += a0.z * b1.x; acc[2][5] += a0.z * b1.y; acc[2][6] += a0.z * b1.z; acc[2][7] += a0.z * b1.w;
            acc[3][0] += a0.w * b0.x; acc[3][1] += a0.w * b0.y; acc[3][2] += a0.w * b0.z; acc[3][3] += a0.w * b0.w;
            acc[3][4] += a0.w * b1.x; acc[3][5] += a0.w * b1.y; acc[3][6] += a0.w * b1.z; acc[3][7] += a0.w * b1.w;
            acc[4][0] += a1.x * b0.x; acc[4][1] += a1.x * b0.y; acc[4][2] += a1.x * b0.z; acc[4][3] += a1.x * b0.w;
            acc[4][4] += a1.x * b1.x; acc[4][5] += a1.x * b1.y; acc[4][6] += a1.x * b1.z; acc[4][7] += a1.x * b1.w;
            acc[5][0] += a1.y * b0.x; acc[5][1] += a1.y * b0.y; acc[5][2] += a1.y * b0.z; acc[5][3] += a1.y * b0.w;
            acc[5][4] += a1.y * b1.x; acc[5][5] += a1.y * b1.y; acc[5][6] += a1.y * b1.z; acc[5][7] += a1.y * b1.w;
            acc[6][0] += a1.z * b0.x; acc[6][1] += a1.z * b0.y; acc[6][2] += a1.z * b0.z; acc[6][3] += a1.z * b0.w;
            acc[6][4] += a1.z * b1.x; acc[6][5] += a1.z * b1.y; acc[6][6] += a1.z * b1.z; acc[6][7] += a1.z * b1.w;
            acc[7][0] += a1.w * b0.x; acc[7][1] += a1.w * b0.y; acc[7][2] += a1.w * b0.z; acc[7][3] += a1.w * b0.w;
            acc[7][4] += a1.w * b1.x; acc[7][5] += a1.w * b1.y; acc[7][6] += a1.w * b1.z; acc[7][7] += a1.w * b1.w;
        }
        __syncthreads();
        if (more) {
#pragma unroll
            for (int j = 0; j < 8; j++) {
                int ia = tid + j * 256;
                As[ia & 15][ia >> 4] = ra[j];
                Bs[ia >> 7][ia & 127] = rb[j];
            }
            __syncthreads();
        }
    }

#pragma unroll
    for (int i = 0; i < 8; i++) {
        int gr = r0 + ty * 8 + i;
        if (gr < n) {
            *(float4*)&H[gr * 128 + tx * 8]     = make_float4(acc[i][0], acc[i][1], acc[i][2], acc[i][3]);
            *(float4*)&H[gr * 128 + tx * 8 + 4] = make_float4(acc[i][4], acc[i][5], acc[i][6], acc[i][7]);
        }
    }
}

// ---------------- layer-2 GEMM: H[n,64] = X[n,128] @ W[128,64] ---------------
// 128x64 block tile, 8x4 micro-tile.
__global__ __launch_bounds__(256) void gemm_l2_kernel(const float* __restrict__ X,
                                                      const float* __restrict__ W,
                                                      float* __restrict__ H, int n) {
    __shared__ __align__(16) float As[16][132];
    __shared__ __align__(16) float Bs[16][64];
    const int tid = threadIdx.x;
    const int tx = tid & 15;
    const int ty = tid >> 4;
    const int r0 = blockIdx.x * 128;

    float acc[8][4];
#pragma unroll
    for (int j = 0; j < 8; j++)
#pragma unroll
        for (int i = 0; i < 4; i++) acc[j][i] = 0.0f;

    float ra[8], rb[4];
#pragma unroll
    for (int j = 0; j < 8; j++) {
        int ia = tid + j * 256;
        int gr = r0 + (ia >> 4);
        ra[j] = (gr < n) ? X[gr * 128 + (ia & 15)] : 0.0f;
    }
#pragma unroll
    for (int j = 0; j < 4; j++) {
        int ib = tid + j * 256;
        rb[j] = W[(ib >> 6) * 64 + (ib & 63)];
    }
#pragma unroll
    for (int j = 0; j < 8; j++) { int ia = tid + j * 256; As[ia & 15][ia >> 4] = ra[j]; }
#pragma unroll
    for (int j = 0; j < 4; j++) { int ib = tid + j * 256; Bs[ib >> 6][ib & 63] = rb[j]; }
    __syncthreads();

    for (int k0 = 16; k0 <= 128; k0 += 16) {
        bool more = (k0 < 128);
        if (more) {
#pragma unroll
            for (int j = 0; j < 8; j++) {
                int ia = tid + j * 256;
                int gr = r0 + (ia >> 4);
                ra[j] = (gr < n) ? X[gr * 128 + k0 + (ia & 15)] : 0.0f;
            }
#pragma unroll
            for (int j = 0; j < 4; j++) {
                int ib = tid + j * 256;
                rb[j] = W[(k0 + (ib >> 6)) * 64 + (ib & 63)];
            }
        }
#pragma unroll
        for (int kk = 0; kk < 16; kk++) {
            float4 a0 = *(const float4*)&As[kk][ty * 8];
            float4 a1 = *(const float4*)&As[kk][ty * 8 + 4];
            float4 b  = *(const float4*)&Bs[kk][tx * 4];
            acc[0][0] += a0.x * b.x; acc[0][1] += a0.x * b.y; acc[0][2] += a0.x * b.z; acc[0][3] += a0.x * b.w;
            acc[1][0] += a0.y * b.x; acc[1][1] += a0.y * b.y; acc[1][2] += a0.y * b.z; acc[1][3] += a0.y * b.w;
            acc[2][0] += a0.z * b.x; acc[2][1] += a0.z * b.y; acc[2][2] += a0.z * b.z; acc[2][3] += a0.z * b.w;
            acc[3][0] += a0.w * b.x; acc[3][1] += a0.w * b.y; acc[3][2] += a0.w * b.z; acc[3][3] += a0.w * b.w;
            acc[4][0] += a1.x * b.x; acc[4][1] += a1.x * b.y; acc[4][2] += a1.x * b.z; acc[4][3] += a1.x * b.w;
            acc[5][0] += a1.y * b.x; acc[5][1] += a1.y * b.y; acc[5][2] += a1.y * b.z; acc[5][3] += a1.y * b.w;
            acc[6][0] += a1.z * b.x; acc[6][1] += a1.z * b.y; acc[6][2] += a1.z * b.z; acc[6][3] += a1.z * b.w;
            acc[7][0] += a1.w * b.x; acc[7][1] += a1.w * b.y; acc[7][2] += a1.w * b.z; acc[7][3] += a1.w * b.w;
        }
        __syncthreads();
        if (more) {
#pragma unroll
            for (int j = 0; j < 8; j++) { int ia = tid + j * 256; As[ia & 15][ia >> 4] = ra[j]; }
#pragma unroll
            for (int j = 0; j < 4; j++) { int ib = tid + j * 256; Bs[ib >> 6][ib & 63] = rb[j]; }
            __syncthreads();
        }
    }

#pragma unroll
    for (int j = 0; j < 8; j++) {
        int gr = r0 + ty * 8 + j;
        if (gr < n)
            *(float4*)&H[gr * 64 + tx * 4] = make_float4(acc[j][0], acc[j][1], acc[j][2], acc[j][3]);
    }
}

// ---------------- CSR aggregation (warp per node) ----------------------------
// out[d] = dinv[d] * sum_e dinv[s]*H[s] + dinv[d]^2 * H[d] + bias (opt relu)
// 8 gathers in flight per iteration (MLP_eff ~= 8), 4 accumulators.
__global__ __launch_bounds__(256) void agg128_kernel(const float* __restrict__ H,
                                                     const float* __restrict__ bias,
                                                     float* __restrict__ out,
                                                     int n, int do_relu) {
    int warp = (blockIdx.x * blockDim.x + threadIdx.x) >> 5;
    int lane = threadIdx.x & 31;
    if (warp >= n) return;

    float4 acc0 = make_float4(0.f, 0.f, 0.f, 0.f);
    float4 acc1 = make_float4(0.f, 0.f, 0.f, 0.f);
    float4 acc2 = make_float4(0.f, 0.f, 0.f, 0.f);
    float4 acc3 = make_float4(0.f, 0.f, 0.f, 0.f);
    int beg = g_rowptr[warp], end = g_rowptr[warp + 1];
    const float4* H4 = (const float4*)H;
    int p = beg;
    for (; p + 7 < end; p += 8) {
        int2 e0 = g_csr[p];     int2 e1 = g_csr[p + 1];
        int2 e2 = g_csr[p + 2]; int2 e3 = g_csr[p + 3];
        int2 e4 = g_csr[p + 4]; int2 e5 = g_csr[p + 5];
        int2 e6 = g_csr[p + 6]; int2 e7 = g_csr[p + 7];
        float4 v0 = H4[e0.x * 32 + lane]; float4 v1 = H4[e1.x * 32 + lane];
        float4 v2 = H4[e2.x * 32 + lane]; float4 v3 = H4[e3.x * 32 + lane];
        float4 v4 = H4[e4.x * 32 + lane]; float4 v5 = H4[e5.x * 32 + lane];
        float4 v6 = H4[e6.x * 32 + lane]; float4 v7 = H4[e7.x * 32 + lane];
        float w0 = __int_as_float(e0.y), w1 = __int_as_float(e1.y);
        float w2 = __int_as_float(e2.y), w3 = __int_as_float(e3.y);
        float w4 = __int_as_float(e4.y), w5 = __int_as_float(e5.y);
        float w6 = __int_as_float(e6.y), w7 = __int_as_float(e7.y);
        acc0.x += w0 * v0.x; acc0.y += w0 * v0.y; acc0.z += w0 * v0.z; acc0.w += w0 * v0.w;
        acc1.x += w1 * v1.x; acc1.y += w1 * v1.y; acc1.z += w1 * v1.z; acc1.w += w1 * v1.w;
        acc2.x += w2 * v2.x; acc2.y += w2 * v2.y; acc2.z += w2 * v2.z; acc2.w += w2 * v2.w;
        acc3.x += w3 * v3.x; acc3.y += w3 * v3.y; acc3.z += w3 * v3.z; acc3.w += w3 * v3.w;
        acc0.x += w4 * v4.x; acc0.y += w4 * v4.y; acc0.z += w4 * v4.z; acc0.w += w4 * v4.w;
        acc1.x += w5 * v5.x; acc1.y += w5 * v5.y; acc1.z += w5 * v5.z; acc1.w += w5 * v5.w;
        acc2.x += w6 * v6.x; acc2.y += w6 * v6.y; acc2.z += w6 * v6.z; acc2.w += w6 * v6.w;
        acc3.x += w7 * v7.x; acc3.y += w7 * v7.y; acc3.z += w7 * v7.z; acc3.w += w7 * v7.w;
    }
    for (; p < end; p++) {
        int2 e0 = g_csr[p];
        float4 v0 = H4[e0.x * 32 + lane];
        float w0 = __int_as_float(e0.y);
        acc0.x += w0 * v0.x; acc0.y += w0 * v0.y; acc0.z += w0 * v0.z; acc0.w += w0 * v0.w;
    }
    acc0.x += acc1.x + acc2.x + acc3.x;
    acc0.y += acc1.y + acc2.y + acc3.y;
    acc0.z += acc1.z + acc2.z + acc3.z;
    acc0.w += acc1.w + acc2.w + acc3.w;

    float di = g_dinv[warp];
    float d2 = di * di;
    float4 hv = H4[warp * 32 + lane];
    float4 bv = ((const float4*)bias)[lane];
    float4 o;
    o.x = di * acc0.x + d2 * hv.x + bv.x;
    o.y = di * acc0.y + d2 * hv.y + bv.y;
    o.z = di * acc0.z + d2 * hv.z + bv.z;
    o.w = di * acc0.w + d2 * hv.w + bv.w;
    if (do_relu) {
        o.x = fmaxf(o.x, 0.f); o.y = fmaxf(o.y, 0.f);
        o.z = fmaxf(o.z, 0.f); o.w = fmaxf(o.w, 0.f);
    }
    ((float4*)out)[warp * 32 + lane] = o;
}

__global__ __launch_bounds__(256) void agg64_kernel(const float* __restrict__ H,
                                                    const float* __restrict__ bias,
                                                    float* __restrict__ out, int n) {
    int warp = (blockIdx.x * blockDim.x + threadIdx.x) >> 5;
    int lane = threadIdx.x & 31;
    if (warp >= n) return;

    float2 acc0 = make_float2(0.f, 0.f);
    float2 acc1 = make_float2(0.f, 0.f);
    float2 acc2 = make_float2(0.f, 0.f);
    float2 acc3 = make_float2(0.f, 0.f);
    int beg = g_rowptr[warp], end = g_rowptr[warp + 1];
    const float2* H2 = (const float2*)H;
    int p = beg;
    for (; p + 7 < end; p += 8) {
        int2 e0 = g_csr[p];     int2 e1 = g_csr[p + 1];
        int2 e2 = g_csr[p + 2]; int2 e3 = g_csr[p + 3];
        int2 e4 = g_csr[p + 4]; int2 e5 = g_csr[p + 5];
        int2 e6 = g_csr[p + 6]; int2 e7 = g_csr[p + 7];
        float2 v0 = H2[e0.x * 32 + lane]; float2 v1 = H2[e1.x * 32 + lane];
        float2 v2 = H2[e2.x * 32 + lane]; float2 v3 = H2[e3.x * 32 + lane];
        float2 v4 = H2[e4.x * 32 + lane]; float2 v5 = H2[e5.x * 32 + lane];
        float2 v6 = H2[e6.x * 32 + lane]; float2 v7 = H2[e7.x * 32 + lane];
        float w0 = __int_as_float(e0.y), w1 = __int_as_float(e1.y);
        float w2 = __int_as_float(e2.y), w3 = __int_as_float(e3.y);
        float w4 = __int_as_float(e4.y), w5 = __int_as_float(e5.y);
        float w6 = __int_as_float(e6.y), w7 = __int_as_float(e7.y);
        acc0.x += w0 * v0.x; acc0.y += w0 * v0.y;
        acc1.x += w1 * v1.x; acc1.y += w1 * v1.y;
        acc2.x += w2 * v2.x; acc2.y += w2 * v2.y;
        acc3.x += w3 * v3.x; acc3.y += w3 * v3.y;
        acc0.x += w4 * v4.x; acc0.y += w4 * v4.y;
        acc1.x += w5 * v5.x; acc1.y += w5 * v5.y;
        acc2.x += w6 * v6.x; acc2.y += w6 * v6.y;
        acc3.x += w7 * v7.x; acc3.y += w7 * v7.y;
    }
    for (; p < end; p++) {
        int2 e0 = g_csr[p];
        float2 v0 = H2[e0.x * 32 + lane];
        float w0 = __int_as_float(e0.y);
        acc0.x += w0 * v0.x; acc0.y += w0 * v0.y;
    }
    acc0.x += acc1.x + acc2.x + acc3.x;
    acc0.y += acc1.y + acc2.y + acc3.y;

    float di = g_dinv[warp];
    float d2 = di * di;
    float2 hv = H2[warp * 32 + lane];
    float2 bv = ((const float2*)bias)[lane];
    float2 o;
    o.x = di * acc0.x + d2 * hv.x + bv.x;
    o.y = di * acc0.y + d2 * hv.y + bv.y;
    ((float2*)out)[warp * 32 + lane] = o;
}

// ---------------- launch ------------------------------------------------------
extern "C" void kernel_launch(void* const* d_in, const int* in_sizes, int n_in,
                              void* d_out, int out_size) {
    const float* x   = (const float*)d_in[0];
    const void*  ei  = d_in[1];
    const float* W1  = (const float*)d_in[2];
    const float* b1  = (const float*)d_in[3];
    const float* W2  = (const float*)d_in[4];
    const float* b2  = (const float*)d_in[5];
    float*       out = (float*)d_out;

    const int N  = in_sizes[0] / DIN;   // 50000
    const int E  = in_sizes[1] / 2;     // 800000
    const int nb = (N + 255) / 256;     // 196

    void *p_h1, *p_a1, *p_h2, *p_deg;
    cudaGetSymbolAddress(&p_h1, g_h1);
    cudaGetSymbolAddress(&p_a1, g_a1);
    cudaGetSymbolAddress(&p_h2, g_h2);
    cudaGetSymbolAddress(&p_deg, g_deg);
    float* h1 = (float*)p_h1;
    float* a1 = (float*)p_a1;
    float* h2 = (float*)p_h2;

    // graph build
    detect_kernel<<<1, 32>>>((const int*)ei);
    cudaMemsetAsync(p_deg, 0, N * sizeof(int));
    count_deg_kernel<<<(E + 255) / 256, 256>>>(ei, E, N);
    scan1_kernel<<<nb, 256>>>(N);
    scan2_kernel<<<1, 256>>>(nb);
    scan3_kernel<<<nb, 256>>>(N, nb);
    fill_csr_kernel<<<(E + 255) / 256, 256>>>(ei, E, N);

    // layer 1: h1 = x @ W1 ; a1 = relu(conv1)
    gemm_l1_kernel<<<(N + 127) / 128, 256>>>(x, W1, h1, N);
    agg128_kernel<<<(N + 7) / 8, 256>>>(h1, b1, a1, N, 1);

    // layer 2: h2 = a1 @ W2 ; out = conv2
    gemm_l2_kernel<<<(N + 127) / 128, 256>>>(a1, W2, h2, N);
    agg64_kernel<<<(N + 7) / 8, 256>>>(h2, b2, out, N);
}

// round 14
// speedup vs baseline: 1.5916x; 1.1397x over previous
#include <cuda_runtime.h>
#include <cuda_bf16.h>
#include <cstdint>

// Problem constants (GCN2: N=50000 nodes, E=800000 edges, 128 -> 128 -> 64)
#define NMAX 50000
#define EMAX 800000
#define DIN  128
#define DHID 128
#define DOUT 64
#define NBLK ((NMAX + 255) / 256)

// ---------------- scratch (device globals; no allocations allowed) ----------
__device__ int   g_is64;
__device__ int   g_deg[NMAX];
__device__ int   g_locexc[NMAX];
__device__ int   g_part[NBLK];
__device__ int   g_rowptr[NMAX + 1];
__device__ int   g_cursor[NMAX];
__device__ __align__(16) int2  g_csr[EMAX];
__device__ float g_dinv[NMAX];
__device__ __align__(16) float g_h1[NMAX * DHID];
__device__ __align__(16) float g_h2[NMAX * DOUT];
// bf16 hi/lo split operands for tensor GEMMs
__device__ __align__(16) __nv_bfloat16 g_xhi[NMAX * DIN];
__device__ __align__(16) __nv_bfloat16 g_xlo[NMAX * DIN];
__device__ __align__(16) __nv_bfloat16 g_a1hi[NMAX * DHID];
__device__ __align__(16) __nv_bfloat16 g_a1lo[NMAX * DHID];
__device__ __align__(16) __nv_bfloat16 g_w1thi[DHID * DIN];   // [n][k]
__device__ __align__(16) __nv_bfloat16 g_w1tlo[DHID * DIN];
__device__ __align__(16) __nv_bfloat16 g_w2thi[DOUT * DHID];  // [n][k]
__device__ __align__(16) __nv_bfloat16 g_w2tlo[DOUT * DHID];

// ---------------- graph build (identical to round-9 passing kernel) ---------
__global__ void detect_kernel(const int* __restrict__ ei32) {
    int lane = threadIdx.x & 31;
    int v = (lane < 16) ? ei32[2 * lane + 1] : 0;
    unsigned nz = __ballot_sync(0xFFFFFFFF, v != 0);
    if (lane == 0) g_is64 = (nz == 0) ? 1 : 0;
}
__device__ __forceinline__ int load_edge(const void* ei, long long idx) {
    if (g_is64) return (int)((const long long*)ei)[idx];
    return ((const int*)ei)[idx];
}
__global__ void count_deg_kernel(const void* __restrict__ ei, int E, int n) {
    int e = blockIdx.x * blockDim.x + threadIdx.x;
    if (e < E) {
        int dst = load_edge(ei, (long long)E + e);
        if ((unsigned)dst < (unsigned)n) atomicAdd(&g_deg[dst], 1);
    }
}
__global__ __launch_bounds__(256) void scan1_kernel(int n) {
    __shared__ int s[256];
    int t = threadIdx.x;
    int i = blockIdx.x * 256 + t;
    int d = (i < n) ? g_deg[i] : 0;
    s[t] = d;
    __syncthreads();
#pragma unroll
    for (int off = 1; off < 256; off <<= 1) {
        int v = (t >= off) ? s[t - off] : 0;
        __syncthreads();
        s[t] += v;
        __syncthreads();
    }
    if (i < n) {
        g_locexc[i] = s[t] - d;
        g_dinv[i]   = rsqrtf((float)d + 1.0f);
    }
    if (t == 255) g_part[blockIdx.x] = s[255];
}
__global__ __launch_bounds__(256) void scan2_kernel(int nb) {
    __shared__ int s[256];
    int t = threadIdx.x;
    s[t] = (t < nb) ? g_part[t] : 0;
    __syncthreads();
#pragma unroll
    for (int off = 1; off < 256; off <<= 1) {
        int v = (t >= off) ? s[t - off] : 0;
        __syncthreads();
        s[t] += v;
        __syncthreads();
    }
    if (t < nb) g_part[t] = s[t];
}
__global__ __launch_bounds__(256) void scan3_kernel(int n, int nb) {
    int b = blockIdx.x;
    int i = b * 256 + threadIdx.x;
    int off = (b == 0) ? 0 : g_part[b - 1];
    if (i < n) {
        int r = off + g_locexc[i];
        g_rowptr[i] = r;
        g_cursor[i] = r;
    }
    if (i == 0) g_rowptr[n] = g_part[nb - 1];
}
__global__ void fill_csr_kernel(const void* __restrict__ ei, int E, int n) {
    int e = blockIdx.x * blockDim.x + threadIdx.x;
    if (e < E) {
        int src = load_edge(ei, e);
        int dst = load_edge(ei, (long long)E + e);
        if ((unsigned)src < (unsigned)n && (unsigned)dst < (unsigned)n) {
            int pos = atomicAdd(&g_cursor[dst], 1);
            g_csr[pos] = make_int2(src, __float_as_int(g_dinv[src]));
        }
    }
}

// ---------------- bf16 hi/lo split helpers -----------------------------------
__device__ __forceinline__ uint32_t pack2(float a, float b, float* ra, float* rb) {
    __nv_bfloat16 ha = __float2bfloat16(a), hb = __float2bfloat16(b);
    *ra = a - __bfloat162float(ha);
    *rb = b - __bfloat162float(hb);
    return (uint32_t)__bfloat16_as_ushort(ha) | ((uint32_t)__bfloat16_as_ushort(hb) << 16);
}
__device__ __forceinline__ uint32_t pack2b(float a, float b) {
    __nv_bfloat16 ha = __float2bfloat16(a), hb = __float2bfloat16(b);
    return (uint32_t)__bfloat16_as_ushort(ha) | ((uint32_t)__bfloat16_as_ushort(hb) << 16);
}

__global__ __launch_bounds__(256) void split_x_kernel(const float* __restrict__ X, int total8) {
    int c = blockIdx.x * blockDim.x + threadIdx.x;
    if (c >= total8) return;
    float4 f0 = ((const float4*)X)[c * 2];
    float4 f1 = ((const float4*)X)[c * 2 + 1];
    float r[8];
    uint4 hi, lo;
    hi.x = pack2(f0.x, f0.y, &r[0], &r[1]);
    hi.y = pack2(f0.z, f0.w, &r[2], &r[3]);
    hi.z = pack2(f1.x, f1.y, &r[4], &r[5]);
    hi.w = pack2(f1.z, f1.w, &r[6], &r[7]);
    lo.x = pack2b(r[0], r[1]); lo.y = pack2b(r[2], r[3]);
    lo.z = pack2b(r[4], r[5]); lo.w = pack2b(r[6], r[7]);
    ((uint4*)g_xhi)[c] = hi;
    ((uint4*)g_xlo)[c] = lo;
}

__global__ __launch_bounds__(256) void split_w_kernel(const float* __restrict__ W1,
                                                      const float* __restrict__ W2) {
    int idx = blockIdx.x * 256 + threadIdx.x;
    if (idx < DIN * DHID) {
        int k = idx >> 7, n_ = idx & 127;       // W1[k][n]
        float v = W1[idx];
        __nv_bfloat16 h = __float2bfloat16(v);
        g_w1thi[n_ * 128 + k] = h;
        g_w1tlo[n_ * 128 + k] = __float2bfloat16(v - __bfloat162float(h));
    }
    if (idx < DHID * DOUT) {
        int k = idx >> 6, n_ = idx & 63;        // W2[k][n]
        float v = W2[idx];
        __nv_bfloat16 h = __float2bfloat16(v);
        g_w2thi[n_ * 128 + k] = h;
        g_w2tlo[n_ * 128 + k] = __float2bfloat16(v - __bfloat162float(h));
    }
}

// ---------------- mma.sync bf16 GEMM -----------------------------------------
// H[n, NCOLS] = A[n,128] @ Bt[NCOLS,128]^T, hi/lo split (3 passes), fp32 accum.
// Block tile 128 x NCOLS, 8 warps = 4 row-groups x 2 col-groups.
// Warp tile 32 x (NCOLS/2). K-slabs of 32, shared k-stride 40 halves
// (20 words -> conflict-free fragment LDS across 8 rows).
__device__ __forceinline__ void mma16816(float* c, const uint32_t* a,
                                         uint32_t b0, uint32_t b1) {
    asm volatile(
        "mma.sync.aligned.m16n8k16.row.col.f32.bf16.bf16.f32 "
        "{%0,%1,%2,%3}, {%4,%5,%6,%7}, {%8,%9}, {%0,%1,%2,%3};"
        : "+f"(c[0]), "+f"(c[1]), "+f"(c[2]), "+f"(c[3])
        : "r"(a[0]), "r"(a[1]), "r"(a[2]), "r"(a[3]), "r"(b0), "r"(b1));
}

template <int NCOLS>
__global__ __launch_bounds__(256) void tgemm_kernel(
    const __nv_bfloat16* __restrict__ Ahi_g, const __nv_bfloat16* __restrict__ Alo_g,
    const __nv_bfloat16* __restrict__ Bhi_g, const __nv_bfloat16* __restrict__ Blo_g,
    float* __restrict__ H, int n)
{
    constexpr int KS = 40;                    // k-stride in halves
    constexpr int NAT = NCOLS / 16;           // n-atoms per warp (8 or 4)
    __shared__ __align__(16) __nv_bfloat16 sAh[128 * KS];
    __shared__ __align__(16) __nv_bfloat16 sAl[128 * KS];
    __shared__ __align__(16) __nv_bfloat16 sBh[NCOLS * KS];
    __shared__ __align__(16) __nv_bfloat16 sBl[NCOLS * KS];

    const int tid = threadIdx.x;
    const int wid = tid >> 5, lane = tid & 31;
    const int g = lane >> 2, tg = lane & 3;
    const int wr = wid & 3;                   // row group: rows wr*32..+31
    const int wc = wid >> 2;                  // col group: cols wc*(NCOLS/2)..
    const int r0 = blockIdx.x * 128;

    float acc[2][NAT][4];
#pragma unroll
    for (int mi = 0; mi < 2; mi++)
#pragma unroll
        for (int ni = 0; ni < NAT; ni++)
#pragma unroll
            for (int q = 0; q < 4; q++) acc[mi][ni][q] = 0.0f;

    for (int s = 0; s < 4; s++) {             // K-slabs of 32
        // A slab: 128 rows x 4 uint4 chunks (hi + lo)
        for (int i = tid; i < 512; i += 256) {
            int row = i >> 2, ch = i & 3;
            int gr = r0 + row;
            uint4 vh = make_uint4(0, 0, 0, 0), vl = vh;
            if (gr < n) {
                vh = ((const uint4*)Ahi_g)[gr * 16 + s * 4 + ch];
                vl = ((const uint4*)Alo_g)[gr * 16 + s * 4 + ch];
            }
            *(uint4*)&sAh[row * KS + ch * 8] = vh;
            *(uint4*)&sAl[row * KS + ch * 8] = vl;
        }
        // B slab: NCOLS rows x 4 chunks (hi + lo)
        for (int i = tid; i < NCOLS * 4; i += 256) {
            int row = i >> 2, ch = i & 3;
            *(uint4*)&sBh[row * KS + ch * 8] = ((const uint4*)Bhi_g)[row * 16 + s * 4 + ch];
            *(uint4*)&sBl[row * KS + ch * 8] = ((const uint4*)Blo_g)[row * 16 + s * 4 + ch];
        }
        __syncthreads();

#pragma unroll
        for (int pass = 0; pass < 3; pass++) {
            const __nv_bfloat16* sA = (pass == 2) ? sAl : sAh;
            const __nv_bfloat16* sB = (pass == 1) ? sBl : sBh;
#pragma unroll
            for (int kk = 0; kk < 2; kk++) {  // two k16 atoms per slab
                uint32_t a[2][4];
#pragma unroll
                for (int mi = 0; mi < 2; mi++) {
                    int rb = (wr * 32 + mi * 16 + g) * KS + kk * 16 + tg * 2;
                    a[mi][0] = *(const uint32_t*)&sA[rb];
                    a[mi][1] = *(const uint32_t*)&sA[rb + 8 * KS];
                    a[mi][2] = *(const uint32_t*)&sA[rb + 8];
                    a[mi][3] = *(const uint32_t*)&sA[rb + 8 * KS + 8];
                }
#pragma unroll
                for (int ni = 0; ni < NAT; ni++) {
                    int nb = (wc * (NCOLS / 2) + ni * 8 + g) * KS + kk * 16 + tg * 2;
                    uint32_t b0 = *(const uint32_t*)&sB[nb];
                    uint32_t b1 = *(const uint32_t*)&sB[nb + 8];
                    mma16816(acc[0][ni], a[0], b0, b1);
                    mma16816(acc[1][ni], a[1], b0, b1);
                }
            }
        }
        __syncthreads();
    }

    // store: thread holds rows {g, g+8} of each m-atom, cols tg*2, tg*2+1
#pragma unroll
    for (int mi = 0; mi < 2; mi++) {
        int r = r0 + wr * 32 + mi * 16 + g;
#pragma unroll
        for (int ni = 0; ni < NAT; ni++) {
            int c = wc * (NCOLS / 2) + ni * 8 + tg * 2;
            if (r < n)
                *(float2*)&H[(long long)r * NCOLS + c] = make_float2(acc[mi][ni][0], acc[mi][ni][1]);
            if (r + 8 < n)
                *(float2*)&H[(long long)(r + 8) * NCOLS + c] = make_float2(acc[mi][ni][2], acc[mi][ni][3]);
        }
    }
}

// ---------------- CSR aggregation (identical gather loop to round 9) ---------
__global__ __launch_bounds__(256) void agg128_kernel(const float* __restrict__ H,
                                                     const float* __restrict__ bias,
                                                     __nv_bfloat16* __restrict__ a1hi,
                                                     __nv_bfloat16* __restrict__ a1lo,
                                                     int n) {
    int warp = (blockIdx.x * blockDim.x + threadIdx.x) >> 5;
    int lane = threadIdx.x & 31;
    if (warp >= n) return;

    float4 acc0 = make_float4(0.f, 0.f, 0.f, 0.f);
    float4 acc1 = make_float4(0.f, 0.f, 0.f, 0.f);
    float4 acc2 = make_float4(0.f, 0.f, 0.f, 0.f);
    float4 acc3 = make_float4(0.f, 0.f, 0.f, 0.f);
    int beg = g_rowptr[warp], end = g_rowptr[warp + 1];
    const float4* H4 = (const float4*)H;
    int p = beg;
    for (; p + 7 < end; p += 8) {
        int2 e0 = g_csr[p];     int2 e1 = g_csr[p + 1];
        int2 e2 = g_csr[p + 2]; int2 e3 = g_csr[p + 3];
        int2 e4 = g_csr[p + 4]; int2 e5 = g_csr[p + 5];
        int2 e6 = g_csr[p + 6]; int2 e7 = g_csr[p + 7];
        float4 v0 = H4[e0.x * 32 + lane]; float4 v1 = H4[e1.x * 32 + lane];
        float4 v2 = H4[e2.x * 32 + lane]; float4 v3 = H4[e3.x * 32 + lane];
        float4 v4 = H4[e4.x * 32 + lane]; float4 v5 = H4[e5.x * 32 + lane];
        float4 v6 = H4[e6.x * 32 + lane]; float4 v7 = H4[e7.x * 32 + lane];
        float w0 = __int_as_float(e0.y), w1 = __int_as_float(e1.y);
        float w2 = __int_as_float(e2.y), w3 = __int_as_float(e3.y);
        float w4 = __int_as_float(e4.y), w5 = __int_as_float(e5.y);
        float w6 = __int_as_float(e6.y), w7 = __int_as_float(e7.y);
        acc0.x += w0 * v0.x; acc0.y += w0 * v0.y; acc0.z += w0 * v0.z; acc0.w += w0 * v0.w;
        acc1.x += w1 * v1.x; acc1.y += w1 * v1.y; acc1.z += w1 * v1.z; acc1.w += w1 * v1.w;
        acc2.x += w2 * v2.x; acc2.y += w2 * v2.y; acc2.z += w2 * v2.z; acc2.w += w2 * v2.w;
        acc3.x += w3 * v3.x; acc3.y += w3 * v3.y; acc3.z += w3 * v3.z; acc3.w += w3 * v3.w;
        acc0.x += w4 * v4.x; acc0.y += w4 * v4.y; acc0.z += w4 * v4.z; acc0.w += w4 * v4.w;
        acc1.x += w5 * v5.x; acc1.y += w5 * v5.y; acc1.z += w5 * v5.z; acc1.w += w5 * v5.w;
        acc2.x += w6 * v6.x; acc2.y += w6 * v6.y; acc2.z += w6 * v6.z; acc2.w += w6 * v6.w;
        acc3.x += w7 * v7.x; acc3.y += w7 * v7.y; acc3.z += w7 * v7.z; acc3.w += w7 * v7.w;
    }
    for (; p < end; p++) {
        int2 e0 = g_csr[p];
        float4 v0 = H4[e0.x * 32 + lane];
        float w0 = __int_as_float(e0.y);
        acc0.x += w0 * v0.x; acc0.y += w0 * v0.y; acc0.z += w0 * v0.z; acc0.w += w0 * v0.w;
    }
    acc0.x += acc1.x + acc2.x + acc3.x;
    acc0.y += acc1.y + acc2.y + acc3.y;
    acc0.z += acc1.z + acc2.z + acc3.z;
    acc0.w += acc1.w + acc2.w + acc3.w;

    float di = g_dinv[warp];
    float d2 = di * di;
    float4 hv = H4[warp * 32 + lane];
    float4 bv = ((const float4*)bias)[lane];
    float4 o;
    o.x = fmaxf(di * acc0.x + d2 * hv.x + bv.x, 0.f);
    o.y = fmaxf(di * acc0.y + d2 * hv.y + bv.y, 0.f);
    o.z = fmaxf(di * acc0.z + d2 * hv.z + bv.z, 0.f);
    o.w = fmaxf(di * acc0.w + d2 * hv.w + bv.w, 0.f);

    float rx, ry, rz, rw;
    uint2 hi, lo;
    hi.x = pack2(o.x, o.y, &rx, &ry);
    hi.y = pack2(o.z, o.w, &rz, &rw);
    lo.x = pack2b(rx, ry);
    lo.y = pack2b(rz, rw);
    ((uint2*)a1hi)[warp * 32 + lane] = hi;
    ((uint2*)a1lo)[warp * 32 + lane] = lo;
}

__global__ __launch_bounds__(256) void agg64_kernel(const float* __restrict__ H,
                                                    const float* __restrict__ bias,
                                                    float* __restrict__ out, int n) {
    int warp = (blockIdx.x * blockDim.x + threadIdx.x) >> 5;
    int lane = threadIdx.x & 31;
    if (warp >= n) return;

    float2 acc0 = make_float2(0.f, 0.f);
    float2 acc1 = make_float2(0.f, 0.f);
    float2 acc2 = make_float2(0.f, 0.f);
    float2 acc3 = make_float2(0.f, 0.f);
    int beg = g_rowptr[warp], end = g_rowptr[warp + 1];
    const float2* H2 = (const float2*)H;
    int p = beg;
    for (; p + 7 < end; p += 8) {
        int2 e0 = g_csr[p];     int2 e1 = g_csr[p + 1];
        int2 e2 = g_csr[p + 2]; int2 e3 = g_csr[p + 3];
        int2 e4 = g_csr[p + 4]; int2 e5 = g_csr[p + 5];
        int2 e6 = g_csr[p + 6]; int2 e7 = g_csr[p + 7];
        float2 v0 = H2[e0.x * 32 + lane]; float2 v1 = H2[e1.x * 32 + lane];
        float2 v2 = H2[e2.x * 32 + lane]; float2 v3 = H2[e3.x * 32 + lane];
        float2 v4 = H2[e4.x * 32 + lane]; float2 v5 = H2[e5.x * 32 + lane];
        float2 v6 = H2[e6.x * 32 + lane]; float2 v7 = H2[e7.x * 32 + lane];
        float w0 = __int_as_float(e0.y), w1 = __int_as_float(e1.y);
        float w2 = __int_as_float(e2.y), w3 = __int_as_float(e3.y);
        float w4 = __int_as_float(e4.y), w5 = __int_as_float(e5.y);
        float w6 = __int_as_float(e6.y), w7 = __int_as_float(e7.y);
        acc0.x += w0 * v0.x; acc0.y += w0 * v0.y;
        acc1.x += w1 * v1.x; acc1.y += w1 * v1.y;
        acc2.x += w2 * v2.x; acc2.y += w2 * v2.y;
        acc3.x += w3 * v3.x; acc3.y += w3 * v3.y;
        acc0.x += w4 * v4.x; acc0.y += w4 * v4.y;
        acc1.x += w5 * v5.x; acc1.y += w5 * v5.y;
        acc2.x += w6 * v6.x; acc2.y += w6 * v6.y;
        acc3.x += w7 * v7.x; acc3.y += w7 * v7.y;
    }
    for (; p < end; p++) {
        int2 e0 = g_csr[p];
        float2 v0 = H2[e0.x * 32 + lane];
        float w0 = __int_as_float(e0.y);
        acc0.x += w0 * v0.x; acc0.y += w0 * v0.y;
    }
    acc0.x += acc1.x + acc2.x + acc3.x;
    acc0.y += acc1.y + acc2.y + acc3.y;

    float di = g_dinv[warp];
    float d2 = di * di;
    float2 hv = H2[warp * 32 + lane];
    float2 bv = ((const float2*)bias)[lane];
    float2 o;
    o.x = di * acc0.x + d2 * hv.x + bv.x;
    o.y = di * acc0.y + d2 * hv.y + bv.y;
    ((float2*)out)[warp * 32 + lane] = o;
}

// ---------------- launch ------------------------------------------------------
extern "C" void kernel_launch(void* const* d_in, const int* in_sizes, int n_in,
                              void* d_out, int out_size) {
    const float* x   = (const float*)d_in[0];
    const void*  ei  = d_in[1];
    const float* W1  = (const float*)d_in[2];
    const float* b1  = (const float*)d_in[3];
    const float* W2  = (const float*)d_in[4];
    const float* b2  = (const float*)d_in[5];
    float*       out = (float*)d_out;

    const int N  = in_sizes[0] / DIN;   // 50000
    const int E  = in_sizes[1] / 2;     // 800000
    const int nb = (N + 255) / 256;     // 196

    void *p_h1, *p_h2, *p_deg, *p_xhi, *p_xlo, *p_a1hi, *p_a1lo;
    void *p_w1h, *p_w1l, *p_w2h, *p_w2l;
    cudaGetSymbolAddress(&p_h1, g_h1);
    cudaGetSymbolAddress(&p_h2, g_h2);
    cudaGetSymbolAddress(&p_deg, g_deg);
    cudaGetSymbolAddress(&p_xhi, g_xhi);
    cudaGetSymbolAddress(&p_xlo, g_xlo);
    cudaGetSymbolAddress(&p_a1hi, g_a1hi);
    cudaGetSymbolAddress(&p_a1lo, g_a1lo);
    cudaGetSymbolAddress(&p_w1h, g_w1thi);
    cudaGetSymbolAddress(&p_w1l, g_w1tlo);
    cudaGetSymbolAddress(&p_w2h, g_w2thi);
    cudaGetSymbolAddress(&p_w2l, g_w2tlo);

    // graph build (unchanged from round 9)
    detect_kernel<<<1, 32>>>((const int*)ei);
    cudaMemsetAsync(p_deg, 0, N * sizeof(int));
    count_deg_kernel<<<(E + 255) / 256, 256>>>(ei, E, N);
    scan1_kernel<<<nb, 256>>>(N);
    scan2_kernel<<<1, 256>>>(nb);
    scan3_kernel<<<nb, 256>>>(N, nb);
    fill_csr_kernel<<<(E + 255) / 256, 256>>>(ei, E, N);

    // operand prep
    split_x_kernel<<<(N * 16 + 255) / 256, 256>>>(x, N * 16);
    split_w_kernel<<<(DIN * DHID + 255) / 256, 256>>>(W1, W2);

    const int gtiles = (N + 127) / 128;

    // layer 1: h1 = x @ W1 (mma.sync) ; a1(hi/lo) = relu(conv1)
    tgemm_kernel<DHID><<<gtiles, 256>>>(
        (const __nv_bfloat16*)p_xhi, (const __nv_bfloat16*)p_xlo,
        (const __nv_bfloat16*)p_w1h, (const __nv_bfloat16*)p_w1l,
        (float*)p_h1, N);
    agg128_kernel<<<(N + 7) / 8, 256>>>((const float*)p_h1, b1,
                                        (__nv_bfloat16*)p_a1hi, (__nv_bfloat16*)p_a1lo, N);

    // layer 2: h2 = a1 @ W2 (mma.sync) ; out = conv2
    tgemm_kernel<DOUT><<<gtiles, 256>>>(
        (const __nv_bfloat16*)p_a1hi, (const __nv_bfloat16*)p_a1lo,
        (const __nv_bfloat16*)p_w2h, (const __nv_bfloat16*)p_w2l,
        (float*)p_h2, N);
    agg64_kernel<<<(N + 7) / 8, 256>>>((const float*)p_h2, b2, out, N);
}

// round 15
// speedup vs baseline: 1.6367x; 1.0284x over previous
#include <cuda_runtime.h>
#include <cuda_bf16.h>
#include <cstdint>

// Problem constants (GCN2: N=50000 nodes, E=800000 edges, 128 -> 128 -> 64)
#define NMAX 50000
#define EMAX 800000
#define DIN  128
#define DHID 128
#define DOUT 64
#define NBLK ((NMAX + 255) / 256)

// ---------------- scratch (device globals; no allocations allowed) ----------
__device__ int   g_deg[NMAX];
__device__ int   g_locexc[NMAX];
__device__ int   g_part[NBLK];
__device__ int   g_rowptr[NMAX + 1];
__device__ int   g_cursor[NMAX];
__device__ __align__(16) int2  g_csr[EMAX];
__device__ float g_dinv[NMAX];
__device__ __align__(16) float g_h1[NMAX * DHID];
__device__ __align__(16) float g_h2[NMAX * DOUT];
// bf16 hi/lo split operands for tensor GEMMs
__device__ __align__(16) __nv_bfloat16 g_a1hi[NMAX * DHID];
__device__ __align__(16) __nv_bfloat16 g_a1lo[NMAX * DHID];
__device__ __align__(16) __nv_bfloat16 g_w1thi[DHID * DIN];   // [n][k]
__device__ __align__(16) __nv_bfloat16 g_w1tlo[DHID * DIN];
__device__ __align__(16) __nv_bfloat16 g_w2thi[DOUT * DHID];  // [n][k]
__device__ __align__(16) __nv_bfloat16 g_w2tlo[DOUT * DHID];

// ---------------- bf16 hi/lo split helpers -----------------------------------
__device__ __forceinline__ uint32_t pack2(float a, float b, float* ra, float* rb) {
    __nv_bfloat16 ha = __float2bfloat16(a), hb = __float2bfloat16(b);
    *ra = a - __bfloat162float(ha);
    *rb = b - __bfloat162float(hb);
    return (uint32_t)__bfloat16_as_ushort(ha) | ((uint32_t)__bfloat16_as_ushort(hb) << 16);
}
__device__ __forceinline__ uint32_t pack2b(float a, float b) {
    __nv_bfloat16 ha = __float2bfloat16(a), hb = __float2bfloat16(b);
    return (uint32_t)__bfloat16_as_ushort(ha) | ((uint32_t)__bfloat16_as_ushort(hb) << 16);
}

// ---------------- per-warp edge dtype detection -------------------------------
// int64 non-negative indices viewed as int32 words: all odd words are zero.
// First 32 ints are L1/L2-hot after the first warp touches them.
__device__ __forceinline__ int warp_is64(const int* __restrict__ ei32) {
    int lane = threadIdx.x & 31;
    int v = (lane < 16) ? ei32[2 * lane + 1] : 0;
    unsigned nz = __ballot_sync(0xFFFFFFFF, v != 0);
    return nz == 0;
}

// ---------------- fused: degree count (edge blocks) + W split (tail blocks) ---
__global__ void count_w_kernel(const void* __restrict__ ei, int E, int n, int eblocks,
                               const float* __restrict__ W1, const float* __restrict__ W2) {
    if (blockIdx.x < (unsigned)eblocks) {
        int is64 = warp_is64((const int*)ei);
        int e = blockIdx.x * 256 + threadIdx.x;
        if (e < E) {
            long long idx = (long long)E + e;
            int dst = is64 ? (int)((const long long*)ei)[idx] : ((const int*)ei)[idx];
            if ((unsigned)dst < (unsigned)n) atomicAdd(&g_deg[dst], 1);
        }
    } else {
        int idx = (blockIdx.x - eblocks) * 256 + threadIdx.x;
        if (idx < DIN * DHID) {
            int k = idx >> 7, n_ = idx & 127;       // W1[k][n]
            float v = W1[idx];
            __nv_bfloat16 h = __float2bfloat16(v);
            g_w1thi[n_ * 128 + k] = h;
            g_w1tlo[n_ * 128 + k] = __float2bfloat16(v - __bfloat162float(h));
        }
        if (idx < DHID * DOUT) {
            int k = idx >> 6, n_ = idx & 63;        // W2[k][n]
            float v = W2[idx];
            __nv_bfloat16 h = __float2bfloat16(v);
            g_w2thi[n_ * 128 + k] = h;
            g_w2tlo[n_ * 128 + k] = __float2bfloat16(v - __bfloat162float(h));
        }
    }
}

// ---------------- 3-phase parallel scan (identical to round 14) ---------------
__global__ __launch_bounds__(256) void scan1_kernel(int n) {
    __shared__ int s[256];
    int t = threadIdx.x;
    int i = blockIdx.x * 256 + t;
    int d = (i < n) ? g_deg[i] : 0;
    s[t] = d;
    __syncthreads();
#pragma unroll
    for (int off = 1; off < 256; off <<= 1) {
        int v = (t >= off) ? s[t - off] : 0;
        __syncthreads();
        s[t] += v;
        __syncthreads();
    }
    if (i < n) {
        g_locexc[i] = s[t] - d;
        g_dinv[i]   = rsqrtf((float)d + 1.0f);
    }
    if (t == 255) g_part[blockIdx.x] = s[255];
}
__global__ __launch_bounds__(256) void scan2_kernel(int nb) {
    __shared__ int s[256];
    int t = threadIdx.x;
    s[t] = (t < nb) ? g_part[t] : 0;
    __syncthreads();
#pragma unroll
    for (int off = 1; off < 256; off <<= 1) {
        int v = (t >= off) ? s[t - off] : 0;
        __syncthreads();
        s[t] += v;
        __syncthreads();
    }
    if (t < nb) g_part[t] = s[t];
}
__global__ __launch_bounds__(256) void scan3_kernel(int n, int nb) {
    int b = blockIdx.x;
    int i = b * 256 + threadIdx.x;
    int off = (b == 0) ? 0 : g_part[b - 1];
    if (i < n) {
        int r = off + g_locexc[i];
        g_rowptr[i] = r;
        g_cursor[i] = r;
    }
    if (i == 0) g_rowptr[n] = g_part[nb - 1];
}
__global__ void fill_csr_kernel(const void* __restrict__ ei, int E, int n) {
    int is64 = warp_is64((const int*)ei);
    int e = blockIdx.x * blockDim.x + threadIdx.x;
    if (e < E) {
        int src, dst;
        if (is64) {
            src = (int)((const long long*)ei)[e];
            dst = (int)((const long long*)ei)[(long long)E + e];
        } else {
            src = ((const int*)ei)[e];
            dst = ((const int*)ei)[(long long)E + e];
        }
        if ((unsigned)src < (unsigned)n && (unsigned)dst < (unsigned)n) {
            int pos = atomicAdd(&g_cursor[dst], 1);
            g_csr[pos] = make_int2(src, __float_as_int(g_dinv[src]));
        }
    }
}

// ---------------- mma.sync bf16 GEMM (round-14 core, AF32 adds fused split) ---
// H[n, NCOLS] = A[n,128] @ Bt[NCOLS,128]^T, hi/lo split (3 passes), fp32 accum.
// AF32=true: A operand is fp32; hi/lo conversion happens in the slab loader.
__device__ __forceinline__ void mma16816(float* c, const uint32_t* a,
                                         uint32_t b0, uint32_t b1) {
    asm volatile(
        "mma.sync.aligned.m16n8k16.row.col.f32.bf16.bf16.f32 "
        "{%0,%1,%2,%3}, {%4,%5,%6,%7}, {%8,%9}, {%0,%1,%2,%3};"
        : "+f"(c[0]), "+f"(c[1]), "+f"(c[2]), "+f"(c[3])
        : "r"(a[0]), "r"(a[1]), "r"(a[2]), "r"(a[3]), "r"(b0), "r"(b1));
}

template <int NCOLS, bool AF32>
__global__ __launch_bounds__(256) void tgemm_kernel(
    const void* __restrict__ Aa, const void* __restrict__ Ab,
    const __nv_bfloat16* __restrict__ Bhi_g, const __nv_bfloat16* __restrict__ Blo_g,
    float* __restrict__ H, int n)
{
    constexpr int KS = 40;                    // k-stride in halves
    constexpr int NAT = NCOLS / 16;           // n-atoms per warp (8 or 4)
    __shared__ __align__(16) __nv_bfloat16 sAh[128 * KS];
    __shared__ __align__(16) __nv_bfloat16 sAl[128 * KS];
    __shared__ __align__(16) __nv_bfloat16 sBh[NCOLS * KS];
    __shared__ __align__(16) __nv_bfloat16 sBl[NCOLS * KS];

    const int tid = threadIdx.x;
    const int wid = tid >> 5, lane = tid & 31;
    const int g = lane >> 2, tg = lane & 3;
    const int wr = wid & 3;                   // row group: rows wr*32..+31
    const int wc = wid >> 2;                  // col group: cols wc*(NCOLS/2)..
    const int r0 = blockIdx.x * 128;

    float acc[2][NAT][4];
#pragma unroll
    for (int mi = 0; mi < 2; mi++)
#pragma unroll
        for (int ni = 0; ni < NAT; ni++)
#pragma unroll
            for (int q = 0; q < 4; q++) acc[mi][ni][q] = 0.0f;

    for (int s = 0; s < 4; s++) {             // K-slabs of 32
        // A slab: 128 rows x 4 chunks of 8 cols (hi + lo)
        for (int i = tid; i < 512; i += 256) {
            int row = i >> 2, ch = i & 3;
            int gr = r0 + row;
            uint4 vh = make_uint4(0, 0, 0, 0), vl = vh;
            if (AF32) {
                if (gr < n) {
                    const float4* X4 = (const float4*)Aa;
                    float4 f0 = X4[gr * 32 + (s * 4 + ch) * 2];
                    float4 f1 = X4[gr * 32 + (s * 4 + ch) * 2 + 1];
                    float rr[8];
                    vh.x = pack2(f0.x, f0.y, &rr[0], &rr[1]);
                    vh.y = pack2(f0.z, f0.w, &rr[2], &rr[3]);
                    vh.z = pack2(f1.x, f1.y, &rr[4], &rr[5]);
                    vh.w = pack2(f1.z, f1.w, &rr[6], &rr[7]);
                    vl.x = pack2b(rr[0], rr[1]); vl.y = pack2b(rr[2], rr[3]);
                    vl.z = pack2b(rr[4], rr[5]); vl.w = pack2b(rr[6], rr[7]);
                }
            } else {
                if (gr < n) {
                    vh = ((const uint4*)Aa)[gr * 16 + s * 4 + ch];
                    vl = ((const uint4*)Ab)[gr * 16 + s * 4 + ch];
                }
            }
            *(uint4*)&sAh[row * KS + ch * 8] = vh;
            *(uint4*)&sAl[row * KS + ch * 8] = vl;
        }
        // B slab: NCOLS rows x 4 chunks (hi + lo)
        for (int i = tid; i < NCOLS * 4; i += 256) {
            int row = i >> 2, ch = i & 3;
            *(uint4*)&sBh[row * KS + ch * 8] = ((const uint4*)Bhi_g)[row * 16 + s * 4 + ch];
            *(uint4*)&sBl[row * KS + ch * 8] = ((const uint4*)Blo_g)[row * 16 + s * 4 + ch];
        }
        __syncthreads();

#pragma unroll
        for (int pass = 0; pass < 3; pass++) {
            const __nv_bfloat16* sA = (pass == 2) ? sAl : sAh;
            const __nv_bfloat16* sB = (pass == 1) ? sBl : sBh;
#pragma unroll
            for (int kk = 0; kk < 2; kk++) {  // two k16 atoms per slab
                uint32_t a[2][4];
#pragma unroll
                for (int mi = 0; mi < 2; mi++) {
                    int rb = (wr * 32 + mi * 16 + g) * KS + kk * 16 + tg * 2;
                    a[mi][0] = *(const uint32_t*)&sA[rb];
                    a[mi][1] = *(const uint32_t*)&sA[rb + 8 * KS];
                    a[mi][2] = *(const uint32_t*)&sA[rb + 8];
                    a[mi][3] = *(const uint32_t*)&sA[rb + 8 * KS + 8];
                }
#pragma unroll
                for (int ni = 0; ni < NAT; ni++) {
                    int nb = (wc * (NCOLS / 2) + ni * 8 + g) * KS + kk * 16 + tg * 2;
                    uint32_t b0 = *(const uint32_t*)&sB[nb];
                    uint32_t b1 = *(const uint32_t*)&sB[nb + 8];
                    mma16816(acc[0][ni], a[0], b0, b1);
                    mma16816(acc[1][ni], a[1], b0, b1);
                }
            }
        }
        __syncthreads();
    }

    // store: thread holds rows {g, g+8} of each m-atom, cols tg*2, tg*2+1
#pragma unroll
    for (int mi = 0; mi < 2; mi++) {
        int r = r0 + wr * 32 + mi * 16 + g;
#pragma unroll
        for (int ni = 0; ni < NAT; ni++) {
            int c = wc * (NCOLS / 2) + ni * 8 + tg * 2;
            if (r < n)
                *(float2*)&H[(long long)r * NCOLS + c] = make_float2(acc[mi][ni][0], acc[mi][ni][1]);
            if (r + 8 < n)
                *(float2*)&H[(long long)(r + 8) * NCOLS + c] = make_float2(acc[mi][ni][2], acc[mi][ni][3]);
        }
    }
}

// ---------------- CSR aggregation (identical gather loop to round 14) ---------
__global__ __launch_bounds__(256) void agg128_kernel(const float* __restrict__ H,
                                                     const float* __restrict__ bias,
                                                     __nv_bfloat16* __restrict__ a1hi,
                                                     __nv_bfloat16* __restrict__ a1lo,
                                                     int n) {
    int warp = (blockIdx.x * blockDim.x + threadIdx.x) >> 5;
    int lane = threadIdx.x & 31;
    if (warp >= n) return;

    float4 acc0 = make_float4(0.f, 0.f, 0.f, 0.f);
    float4 acc1 = make_float4(0.f, 0.f, 0.f, 0.f);
    float4 acc2 = make_float4(0.f, 0.f, 0.f, 0.f);
    float4 acc3 = make_float4(0.f, 0.f, 0.f, 0.f);
    int beg = g_rowptr[warp], end = g_rowptr[warp + 1];
    const float4* H4 = (const float4*)H;
    int p = beg;
    for (; p + 7 < end; p += 8) {
        int2 e0 = g_csr[p];     int2 e1 = g_csr[p + 1];
        int2 e2 = g_csr[p + 2]; int2 e3 = g_csr[p + 3];
        int2 e4 = g_csr[p + 4]; int2 e5 = g_csr[p + 5];
        int2 e6 = g_csr[p + 6]; int2 e7 = g_csr[p + 7];
        float4 v0 = H4[e0.x * 32 + lane]; float4 v1 = H4[e1.x * 32 + lane];
        float4 v2 = H4[e2.x * 32 + lane]; float4 v3 = H4[e3.x * 32 + lane];
        float4 v4 = H4[e4.x * 32 + lane]; float4 v5 = H4[e5.x * 32 + lane];
        float4 v6 = H4[e6.x * 32 + lane]; float4 v7 = H4[e7.x * 32 + lane];
        float w0 = __int_as_float(e0.y), w1 = __int_as_float(e1.y);
        float w2 = __int_as_float(e2.y), w3 = __int_as_float(e3.y);
        float w4 = __int_as_float(e4.y), w5 = __int_as_float(e5.y);
        float w6 = __int_as_float(e6.y), w7 = __int_as_float(e7.y);
        acc0.x += w0 * v0.x; acc0.y += w0 * v0.y; acc0.z += w0 * v0.z; acc0.w += w0 * v0.w;
        acc1.x += w1 * v1.x; acc1.y += w1 * v1.y; acc1.z += w1 * v1.z; acc1.w += w1 * v1.w;
        acc2.x += w2 * v2.x; acc2.y += w2 * v2.y; acc2.z += w2 * v2.z; acc2.w += w2 * v2.w;
        acc3.x += w3 * v3.x; acc3.y += w3 * v3.y; acc3.z += w3 * v3.z; acc3.w += w3 * v3.w;
        acc0.x += w4 * v4.x; acc0.y += w4 * v4.y; acc0.z += w4 * v4.z; acc0.w += w4 * v4.w;
        acc1.x += w5 * v5.x; acc1.y += w5 * v5.y; acc1.z += w5 * v5.z; acc1.w += w5 * v5.w;
        acc2.x += w6 * v6.x; acc2.y += w6 * v6.y; acc2.z += w6 * v6.z; acc2.w += w6 * v6.w;
        acc3.x += w7 * v7.x; acc3.y += w7 * v7.y; acc3.z += w7 * v7.z; acc3.w += w7 * v7.w;
    }
    for (; p < end; p++) {
        int2 e0 = g_csr[p];
        float4 v0 = H4[e0.x * 32 + lane];
        float w0 = __int_as_float(e0.y);
        acc0.x += w0 * v0.x; acc0.y += w0 * v0.y; acc0.z += w0 * v0.z; acc0.w += w0 * v0.w;
    }
    acc0.x += acc1.x + acc2.x + acc3.x;
    acc0.y += acc1.y + acc2.y + acc3.y;
    acc0.z += acc1.z + acc2.z + acc3.z;
    acc0.w += acc1.w + acc2.w + acc3.w;

    float di = g_dinv[warp];
    float d2 = di * di;
    float4 hv = H4[warp * 32 + lane];
    float4 bv = ((const float4*)bias)[lane];
    float4 o;
    o.x = fmaxf(di * acc0.x + d2 * hv.x + bv.x, 0.f);
    o.y = fmaxf(di * acc0.y + d2 * hv.y + bv.y, 0.f);
    o.z = fmaxf(di * acc0.z + d2 * hv.z + bv.z, 0.f);
    o.w = fmaxf(di * acc0.w + d2 * hv.w + bv.w, 0.f);

    float rx, ry, rz, rw;
    uint2 hi, lo;
    hi.x = pack2(o.x, o.y, &rx, &ry);
    hi.y = pack2(o.z, o.w, &rz, &rw);
    lo.x = pack2b(rx, ry);
    lo.y = pack2b(rz, rw);
    ((uint2*)a1hi)[warp * 32 + lane] = hi;
    ((uint2*)a1lo)[warp * 32 + lane] = lo;
}

__global__ __launch_bounds__(256) void agg64_kernel(const float* __restrict__ H,
                                                    const float* __restrict__ bias,
                                                    float* __restrict__ out, int n) {
    int warp = (blockIdx.x * blockDim.x + threadIdx.x) >> 5;
    int lane = threadIdx.x & 31;
    if (warp >= n) return;

    float2 acc0 = make_float2(0.f, 0.f);
    float2 acc1 = make_float2(0.f, 0.f);
    float2 acc2 = make_float2(0.f, 0.f);
    float2 acc3 = make_float2(0.f, 0.f);
    int beg = g_rowptr[warp], end = g_rowptr[warp + 1];
    const float2* H2 = (const float2*)H;
    int p = beg;
    for (; p + 7 < end; p += 8) {
        int2 e0 = g_csr[p];     int2 e1 = g_csr[p + 1];
        int2 e2 = g_csr[p + 2]; int2 e3 = g_csr[p + 3];
        int2 e4 = g_csr[p + 4]; int2 e5 = g_csr[p + 5];
        int2 e6 = g_csr[p + 6]; int2 e7 = g_csr[p + 7];
        float2 v0 = H2[e0.x * 32 + lane]; float2 v1 = H2[e1.x * 32 + lane];
        float2 v2 = H2[e2.x * 32 + lane]; float2 v3 = H2[e3.x * 32 + lane];
        float2 v4 = H2[e4.x * 32 + lane]; float2 v5 = H2[e5.x * 32 + lane];
        float2 v6 = H2[e6.x * 32 + lane]; float2 v7 = H2[e7.x * 32 + lane];
        float w0 = __int_as_float(e0.y), w1 = __int_as_float(e1.y);
        float w2 = __int_as_float(e2.y), w3 = __int_as_float(e3.y);
        float w4 = __int_as_float(e4.y), w5 = __int_as_float(e5.y);
        float w6 = __int_as_float(e6.y), w7 = __int_as_float(e7.y);
        acc0.x += w0 * v0.x; acc0.y += w0 * v0.y;
        acc1.x += w1 * v1.x; acc1.y += w1 * v1.y;
        acc2.x += w2 * v2.x; acc2.y += w2 * v2.y;
        acc3.x += w3 * v3.x; acc3.y += w3 * v3.y;
        acc0.x += w4 * v4.x; acc0.y += w4 * v4.y;
        acc1.x += w5 * v5.x; acc1.y += w5 * v5.y;
        acc2.x += w6 * v6.x; acc2.y += w6 * v6.y;
        acc3.x += w7 * v7.x; acc3.y += w7 * v7.y;
    }
    for (; p < end; p++) {
        int2 e0 = g_csr[p];
        float2 v0 = H2[e0.x * 32 + lane];
        float w0 = __int_as_float(e0.y);
        acc0.x += w0 * v0.x; acc0.y += w0 * v0.y;
    }
    acc0.x += acc1.x + acc2.x + acc3.x;
    acc0.y += acc1.y + acc2.y + acc3.y;

    float di = g_dinv[warp];
    float d2 = di * di;
    float2 hv = H2[warp * 32 + lane];
    float2 bv = ((const float2*)bias)[lane];
    float2 o;
    o.x = di * acc0.x + d2 * hv.x + bv.x;
    o.y = di * acc0.y + d2 * hv.y + bv.y;
    ((float2*)out)[warp * 32 + lane] = o;
}

// ---------------- launch ------------------------------------------------------
extern "C" void kernel_launch(void* const* d_in, const int* in_sizes, int n_in,
                              void* d_out, int out_size) {
    const float* x   = (const float*)d_in[0];
    const void*  ei  = d_in[1];
    const float* W1  = (const float*)d_in[2];
    const float* b1  = (const float*)d_in[3];
    const float* W2  = (const float*)d_in[4];
    const float* b2  = (const float*)d_in[5];
    float*       out = (float*)d_out;

    const int N  = in_sizes[0] / DIN;   // 50000
    const int E  = in_sizes[1] / 2;     // 800000
    const int nb = (N + 255) / 256;     // 196
    const int eblocks = (E + 255) / 256;
    const int wblocks = (DIN * DHID + 255) / 256;  // 64

    void *p_h1, *p_h2, *p_deg, *p_a1hi, *p_a1lo;
    void *p_w1h, *p_w1l, *p_w2h, *p_w2l;
    cudaGetSymbolAddress(&p_h1, g_h1);
    cudaGetSymbolAddress(&p_h2, g_h2);
    cudaGetSymbolAddress(&p_deg, g_deg);
    cudaGetSymbolAddress(&p_a1hi, g_a1hi);
    cudaGetSymbolAddress(&p_a1lo, g_a1lo);
    cudaGetSymbolAddress(&p_w1h, g_w1thi);
    cudaGetSymbolAddress(&p_w1l, g_w1tlo);
    cudaGetSymbolAddress(&p_w2h, g_w2thi);
    cudaGetSymbolAddress(&p_w2l, g_w2tlo);

    // graph build + W split (fused launch)
    cudaMemsetAsync(p_deg, 0, N * sizeof(int));
    count_w_kernel<<<eblocks + wblocks, 256>>>(ei, E, N, eblocks, W1, W2);
    scan1_kernel<<<nb, 256>>>(N);
    scan2_kernel<<<1, 256>>>(nb);
    scan3_kernel<<<nb, 256>>>(N, nb);
    fill_csr_kernel<<<eblocks, 256>>>(ei, E, N);

    const int gtiles = (N + 127) / 128;

    // layer 1: h1 = x @ W1 (mma.sync, fused fp32->hi/lo split) ; a1 = relu(conv1)
    tgemm_kernel<DHID, true><<<gtiles, 256>>>(
        x, nullptr,
        (const __nv_bfloat16*)p_w1h, (const __nv_bfloat16*)p_w1l,
        (float*)p_h1, N);
    agg128_kernel<<<(N + 7) / 8, 256>>>((const float*)p_h1, b1,
                                        (__nv_bfloat16*)p_a1hi, (__nv_bfloat16*)p_a1lo, N);

    // layer 2: h2 = a1 @ W2 (mma.sync) ; out = conv2
    tgemm_kernel<DOUT, false><<<gtiles, 256>>>(
        p_a1hi, p_a1lo,
        (const __nv_bfloat16*)p_w2h, (const __nv_bfloat16*)p_w2l,
        (float*)p_h2, N);
    agg64_kernel<<<(N + 7) / 8, 256>>>((const float*)p_h2, b2, out, N);
}